// round 16
// baseline (speedup 1.0000x reference)
#include <cuda_runtime.h>
#include <math.h>
#include <stdint.h>

// ---------------------------------------------------------------- dims
constexpr int MDIM = 2048, KDIM = 2048, NDIM = 256;

// ---------------------------------------------------------------- tiling
constexpr int BM = 64, BN = 64;
constexpr int THREADS = 512;                 // 16 warps: 4 (m) x 4 (n)
constexpr int NWARP = THREADS / 32;
constexpr int STAGES = 5;                    // k128 super-stages
constexpr int PREF = 4;
constexpr int NIT = KDIM / 128;              // 16
constexpr int NSTEPS = 255;                  // recurrence steps 2..256
// packed swizzled tile: 64 rows x 64 B = 4096 B
constexpr int TILE_B = 4096;
constexpr int KT_B   = 2 * TILE_B;           // digit1|digit2 per k64 = 8192
constexpr int BLK_B  = 32 * KT_B;            // per 64-row block = 262144
constexpr int STAGE_BYTES = 4 * KT_B;        // A(k128) + B(k128) = 32768
constexpr int SM_STAGE0 = 1024;
constexpr int SM_STG = SM_STAGE0 + STAGES * STAGE_BYTES;       // epi staging
constexpr int SMEM_BYTES = SM_STG + 2 * TILE_B;                // 173056

// blobs: [blk64][k64][digit1 4K | digit2 4K]
constexpr size_t WBLOB = 32ull * BLK_B;
constexpr size_t HBLOB = 4ull * BLK_B;

// ---------------------------------------------------------------- scratch
__device__ __align__(128) int8_t g_Whx[WBLOB];
__device__ __align__(128) int8_t g_Whh[WBLOB];
__device__ __align__(128) int8_t g_Wph[WBLOB];
__device__ __align__(128) int8_t g_x [HBLOB];
__device__ __align__(128) int8_t g_h0[HBLOB];
__device__ __align__(128) int8_t g_h1[HBLOB];
__device__ float g_c[MDIM * NDIM];
__device__ float g_p[MDIM * NDIM];
__device__ int   g_maxbits[4];
// dataflow flags: index = buf*128 + blob*32 + tile
__device__ int g_wflag[256];
__device__ int g_rcnt [256];

// swizzled byte offset within a packed tile: logical (row, col) 64x64
__device__ __forceinline__ uint32_t tswz(int row, int col) {
    return (uint32_t)(row * 64 + (((col & 48) ^ (((row >> 1) & 3) << 4)) |
                                  (col & 15)));
}

// ---------------------------------------------------------------- helpers
__device__ __forceinline__ uint32_t smem_u32(const void* p) {
    uint32_t a;
    asm("{ .reg .u64 t; cvta.to.shared.u64 t, %1; cvt.u32.u64 %0, t; }"
        : "=r"(a) : "l"(p));
    return a;
}

__device__ __forceinline__ void mma_s8(int* c, const uint32_t* a,
                                       const uint32_t* b) {
    asm volatile(
        "mma.sync.aligned.m16n8k32.row.col.s32.s8.s8.s32 "
        "{%0,%1,%2,%3}, {%4,%5,%6,%7}, {%8,%9}, {%0,%1,%2,%3};"
        : "+r"(c[0]), "+r"(c[1]), "+r"(c[2]), "+r"(c[3])
        : "r"(a[0]), "r"(a[1]), "r"(a[2]), "r"(a[3]), "r"(b[0]), "r"(b[1]));
}

__device__ __forceinline__ void ldsm_x4(uint32_t* r, uint32_t addr) {
    asm volatile("ldmatrix.sync.aligned.m8n8.x4.shared.b16 {%0,%1,%2,%3}, [%4];"
                 : "=r"(r[0]), "=r"(r[1]), "=r"(r[2]), "=r"(r[3]) : "r"(addr));
}

__device__ __forceinline__ void bulkcp(uint32_t sdst, const void* gsrc,
                                       uint32_t bytes, uint32_t mbar) {
    asm volatile(
        "cp.async.bulk.shared::cta.global.mbarrier::complete_tx::bytes "
        "[%0], [%1], %2, [%3];"
        :: "r"(sdst), "l"(gsrc), "r"(bytes), "r"(mbar) : "memory");
}

__device__ __forceinline__ void mbar_init(uint32_t mbar, uint32_t cnt) {
    asm volatile("mbarrier.init.shared.b64 [%0], %1;"
                 :: "r"(mbar), "r"(cnt) : "memory");
}

__device__ __forceinline__ void mbar_expect_tx(uint32_t mbar, uint32_t bytes) {
    asm volatile("mbarrier.arrive.expect_tx.shared.b64 _, [%0], %1;"
                 :: "r"(mbar), "r"(bytes) : "memory");
}

__device__ __forceinline__ void mbar_arrive(uint32_t mbar) {
    asm volatile("mbarrier.arrive.shared.b64 _, [%0];"
                 :: "r"(mbar) : "memory");
}

__device__ __forceinline__ void mbar_wait(uint32_t mb, uint32_t parity) {
    asm volatile(
        "{\n\t.reg .pred P;\n\t"
        "L0_%=:\n\t"
        "mbarrier.try_wait.parity.acquire.cta.shared::cta.b64 P, [%0], %1, 0x989680;\n\t"
        "@P bra.uni L1_%=;\n\t"
        "bra.uni L0_%=;\n\t"
        "L1_%=:\n\t}"
        :: "r"(mb), "r"(parity) : "memory");
}

__device__ __forceinline__ void mbar_wait_relaxed(uint32_t mb, uint32_t parity) {
    asm volatile(
        "{\n\t.reg .pred P;\n\t"
        "L0_%=:\n\t"
        "mbarrier.try_wait.parity.relaxed.cta.shared::cta.b64 P, [%0], %1, 0x989680;\n\t"
        "@P bra.uni L1_%=;\n\t"
        "bra.uni L0_%=;\n\t"
        "L1_%=:\n\t}"
        :: "r"(mb), "r"(parity) : "memory");
}

__device__ __forceinline__ int ld_acq(const int* p) {
    int v;
    asm volatile("ld.global.acquire.gpu.s32 %0, [%1];" : "=r"(v) : "l"(p));
    return v;
}

__device__ __forceinline__ void st_rel(int* p, int v) {
    asm volatile("st.global.release.gpu.s32 [%0], %1;" :: "l"(p), "r"(v)
                 : "memory");
}

__device__ __forceinline__ void quant2(float q, int8_t& d1, int8_t& d2) {
    float b1 = rintf(q);
    float b2 = rintf((q - b1) * 256.0f);
    b2 = fminf(fmaxf(b2, -127.0f), 127.0f);
    d1 = (int8_t)(int)b1;
    d2 = (int8_t)(int)b2;
}

// ---------------------------------------------------------------- prep
__global__ void reset_kernel() {
    if (threadIdx.x < 4) g_maxbits[threadIdx.x] = 0;
    g_wflag[threadIdx.x] = 0;
    g_rcnt[threadIdx.x] = 0;
}

__global__ void maxabs_kernel(const float* __restrict__ w0,
                              const float* __restrict__ w1,
                              const float* __restrict__ w2,
                              const float* __restrict__ x) {
    const int t = blockIdx.y;
    const float* src = (t == 0) ? w0 : (t == 1) ? w1 : (t == 2) ? w2 : x;
    const int len = (t == 3) ? KDIM * NDIM : MDIM * KDIM;
    float m = 0.0f;
    for (int i = blockIdx.x * 256 + threadIdx.x; i < len; i += 2048 * 256)
        m = fmaxf(m, fabsf(src[i]));
    #pragma unroll
    for (int o = 16; o > 0; o >>= 1)
        m = fmaxf(m, __shfl_xor_sync(~0u, m, o));
    if ((threadIdx.x & 31) == 0)
        atomicMax(&g_maxbits[t], __float_as_int(m));
}

__global__ void quant_kernel(const float* __restrict__ w0,
                             const float* __restrict__ w1,
                             const float* __restrict__ w2,
                             const float* __restrict__ x) {
    const int t = blockIdx.y;
    const int len = (t == 3) ? KDIM * NDIM : MDIM * KDIM;
    const int i = blockIdx.x * 256 + threadIdx.x;
    if (i >= len) return;
    const float mx = fmaxf(__int_as_float(g_maxbits[t]), 1e-20f);
    const float iq = 127.0f / mx;
    int8_t d1, d2;
    if (t == 3) {
        const int k = i / NDIM, n = i % NDIM;
        quant2(x[i] * iq, d1, d2);
        const size_t off = (size_t)(n >> 6) * BLK_B + (size_t)(k >> 6) * KT_B +
                           tswz(n & 63, k & 63);
        g_x[off] = d1;
        g_x[off + TILE_B] = d2;
    } else {
        const int m = i >> 11, k = i & 2047;
        const float* w = (t == 0) ? w0 : (t == 1) ? w1 : w2;
        int8_t* o = (t == 0) ? g_Whx : (t == 1) ? g_Whh : g_Wph;
        quant2(w[i] * iq, d1, d2);
        const size_t off = (size_t)(m >> 6) * BLK_B + (size_t)(k >> 6) * KT_B +
                           tswz(m & 63, k & 63);
        o[off] = d1;
        o[off + TILE_B] = d2;
    }
}

__global__ void first_step_kernel(const float* __restrict__ c,
                                  const float* __restrict__ bh,
                                  int8_t* __restrict__ outH) {
    const int i = blockIdx.x * 256 + threadIdx.x;
    if (i >= MDIM * NDIM) return;
    const int n = i >> 11, m = i & 2047;
    const float v = tanhf(c[(size_t)m * NDIM + n] + bh[n]);
    int8_t d1, d2;
    quant2(v * 127.0f, d1, d2);
    const size_t off = (size_t)(n >> 6) * BLK_B + (size_t)(m >> 6) * KT_B +
                       tswz(n & 63, m & 63);
    outH[off] = d1;
    outH[off + TILE_B] = d2;
}

// ---------------------------------------------------------------- single GEMM
__global__ void __launch_bounds__(THREADS) rnn_gemm(
    const int8_t* __restrict__ A, const int8_t* __restrict__ B,
    const int* __restrict__ maxA, const int* __restrict__ maxB,
    const float* __restrict__ bias, float* __restrict__ outF, int mode)
{
    extern __shared__ __align__(16) char sm[];
    const uint32_t sbase = smem_u32(sm);
    const int tid  = threadIdx.x;
    const int lane = tid & 31;
    const int wid  = tid >> 5;
    const int wm0  = (wid & 3) * 16;
    const int wn0  = (wid >> 2) * 16;
    const int mblk = blockIdx.y;
    const int nblk = blockIdx.x;
    const int m0   = mblk * BM;
    const int n0   = nblk * BN;

    auto fullb  = [&](int s) { return sbase + (uint32_t)s * 16; };
    auto emptyb = [&](int s) { return sbase + (uint32_t)s * 16 + 8; };

    const float sa  = __int_as_float(*maxA) * (1.0f / 127.0f);
    const float sb  = maxB ? __int_as_float(*maxB) * (1.0f / 127.0f)
                           : (1.0f / 127.0f);
    const float sAB = sa * sb;

    int C1[2][4] = {};
    int C2[2][4] = {};

    const uint32_t arow = (uint32_t)((wm0 + (lane & 15)) * 64);
    const uint32_t achk = (uint32_t)((lane >> 4) * 16);
    const uint32_t aswz = (uint32_t)((((lane & 15) >> 1) & 3) << 4);
    const uint32_t brow = (uint32_t)((wn0 + (lane & 7) + ((lane >> 4) & 1) * 8) * 64);
    const uint32_t bchk = (uint32_t)(((lane >> 3) & 1) * 16);
    const uint32_t bswz = (uint32_t)(((((lane & 7) + ((lane >> 4) & 1) * 8) >> 1) & 3) << 4);

    if (tid == 0) {
        #pragma unroll
        for (int s = 0; s < STAGES; ++s) {
            mbar_init(fullb(s), 1);
            mbar_init(emptyb(s), NWARP);
        }
        asm volatile("fence.proxy.async.shared::cta;" ::: "memory");
    }
    __syncthreads();

    auto issue_stage = [&](int j) {
        const int s = j % STAGES;
        if (j >= STAGES)
            mbar_wait_relaxed(emptyb(s), (uint32_t)((j / STAGES - 1) & 1));
        const uint32_t dst = sbase + SM_STAGE0 + s * STAGE_BYTES;
        mbar_expect_tx(fullb(s), STAGE_BYTES);
        bulkcp(dst, A + (size_t)mblk * BLK_B + (size_t)(2 * j) * KT_B,
               2 * KT_B, fullb(s));
        bulkcp(dst + 2 * KT_B, B + (size_t)nblk * BLK_B + (size_t)(2 * j) * KT_B,
               2 * KT_B, fullb(s));
    };

    if (tid == 0) {
        #pragma unroll
        for (int s = 0; s < PREF; ++s) issue_stage(s);
    }

    for (int it = 0; it < NIT; ++it) {
        if (tid == 0 && it + PREF < NIT) issue_stage(it + PREF);
        const int s = it % STAGES;
        mbar_wait(fullb(s), (uint32_t)((it / STAGES) & 1));
        const uint32_t st = sbase + SM_STAGE0 + s * STAGE_BYTES;
        #pragma unroll
        for (int h = 0; h < 2; ++h) {
            const uint32_t sA1 = st + h * KT_B;
            const uint32_t sB1 = st + 2 * KT_B + h * KT_B;
            #pragma unroll
            for (int kk = 0; kk < 2; ++kk) {
                const uint32_t ka = ((kk * 32) | achk) ^ aswz;
                const uint32_t kb2 = ((kk * 32) | bchk) ^ bswz;
                uint32_t a1f[4], a2f[4], b1f[4], b2f[4];
                ldsm_x4(a1f, sA1 + arow + ka);
                ldsm_x4(a2f, sA1 + TILE_B + arow + ka);
                ldsm_x4(b1f, sB1 + brow + kb2);
                ldsm_x4(b2f, sB1 + TILE_B + brow + kb2);
                #pragma unroll
                for (int nt = 0; nt < 2; ++nt) {
                    mma_s8(C1[nt], a1f, &b1f[nt * 2]);
                    mma_s8(C2[nt], a1f, &b2f[nt * 2]);
                    mma_s8(C2[nt], a2f, &b1f[nt * 2]);
                }
            }
        }
        if (lane == 0) mbar_arrive(emptyb(s));
    }

    #pragma unroll
    for (int nt = 0; nt < 2; ++nt) {
        const int lr = wm0 + (lane >> 2);
        const int lc = wn0 + nt * 8 + 2 * (lane & 3);
        const int gm = m0 + lr, gn = n0 + lc;
        float bx = 0.f, by = 0.f;
        if (mode == 1) {
            float2 bv = *(const float2*)(bias + gn);
            bx = bv.x; by = bv.y;
        }
        float2 o0, o1;
        o0.x = sAB * ((float)C1[nt][0] + (float)C2[nt][0] * (1.0f / 256.0f)) + bx;
        o0.y = sAB * ((float)C1[nt][1] + (float)C2[nt][1] * (1.0f / 256.0f)) + by;
        o1.x = sAB * ((float)C1[nt][2] + (float)C2[nt][2] * (1.0f / 256.0f)) + bx;
        o1.y = sAB * ((float)C1[nt][3] + (float)C2[nt][3] * (1.0f / 256.0f)) + by;
        *(float2*)(outF + (size_t)gm * NDIM + gn) = o0;
        *(float2*)(outF + (size_t)(gm + 8) * NDIM + gn) = o1;
    }
}

// ---------------------------------------------------------------- persistent
// All 255 recurrence steps, one kernel, 128 co-resident CTAs.
// No global barrier: per-tile write flags + read counters.
__global__ void __launch_bounds__(THREADS) rnn_steps(
    const int8_t* __restrict__ A,
    int8_t* __restrict__ hb0, int8_t* __restrict__ hb1,
    const int* __restrict__ maxA,
    const float* __restrict__ addc, const float* __restrict__ bias)
{
    extern __shared__ __align__(16) char sm[];
    const uint32_t sbase = smem_u32(sm);
    const int tid  = threadIdx.x;
    const int lane = tid & 31;
    const int wid  = tid >> 5;
    const int wm0  = (wid & 3) * 16;
    const int wn0  = (wid >> 2) * 16;
    const int mblk = blockIdx.y;
    const int nblk = blockIdx.x;
    const int m0   = mblk * BM;
    const int n0   = nblk * BN;

    auto fullA  = [&](int s) { return sbase + (uint32_t)s * 24; };
    auto fullB  = [&](int s) { return sbase + (uint32_t)s * 24 + 8; };
    auto emptyb = [&](int s) { return sbase + (uint32_t)s * 24 + 16; };

    const float sa  = __int_as_float(*maxA) * (1.0f / 127.0f);
    const float sAB = sa * (1.0f / 127.0f);

    const uint32_t arow = (uint32_t)((wm0 + (lane & 15)) * 64);
    const uint32_t achk = (uint32_t)((lane >> 4) * 16);
    const uint32_t aswz = (uint32_t)((((lane & 15) >> 1) & 3) << 4);
    const uint32_t brow = (uint32_t)((wn0 + (lane & 7) + ((lane >> 4) & 1) * 8) * 64);
    const uint32_t bchk = (uint32_t)(((lane >> 3) & 1) * 16);
    const uint32_t bswz = (uint32_t)(((((lane & 7) + ((lane >> 4) & 1) * 8) >> 1) & 3) << 4);

    // hoist c + bh (constant across steps)
    float cb[2][4];
    #pragma unroll
    for (int nt = 0; nt < 2; ++nt) {
        const int gm = m0 + wm0 + (lane >> 2);
        const int gn = n0 + wn0 + nt * 8 + 2 * (lane & 3);
        float2 c0 = *(const float2*)(addc + (size_t)gm * NDIM + gn);
        float2 c1 = *(const float2*)(addc + (size_t)(gm + 8) * NDIM + gn);
        float2 bv = *(const float2*)(bias + gn);
        cb[nt][0] = c0.x + bv.x;
        cb[nt][1] = c0.y + bv.y;
        cb[nt][2] = c1.x + bv.x;
        cb[nt][3] = c1.y + bv.y;
    }

    if (tid == 0) {
        #pragma unroll
        for (int s = 0; s < STAGES; ++s) {
            mbar_init(fullA(s), 1);
            mbar_init(fullB(s), 1);
            mbar_init(emptyb(s), NWARP);
        }
        asm volatile("fence.proxy.async.shared::cta;" ::: "memory");
    }
    __syncthreads();

    const int8_t* Ab = A + (size_t)mblk * BLK_B;

    auto issueA = [&](int j) {
        const int s = j % STAGES;
        if (j >= STAGES)
            mbar_wait_relaxed(emptyb(s), (uint32_t)((j / STAGES - 1) & 1));
        const uint32_t dst = sbase + SM_STAGE0 + s * STAGE_BYTES;
        mbar_expect_tx(fullA(s), 2 * KT_B);
        bulkcp(dst, Ab + (size_t)(2 * (j % NIT)) * KT_B, 2 * KT_B, fullA(s));
    };
    // issueB for step t: spins per-tile write flags, then copies
    auto issueB = [&](int j, int t, const int8_t* Bblob) {
        const int s = j % STAGES;
        const int v = t & 1;
        const int kt0 = 2 * (j % NIT);
        const int* f0 = &g_wflag[v * 128 + nblk * 32 + kt0];
        while (ld_acq(f0) < t) {}
        while (ld_acq(f0 + 1) < t) {}
        const uint32_t dst = sbase + SM_STAGE0 + s * STAGE_BYTES + 2 * KT_B;
        mbar_expect_tx(fullB(s), 2 * KT_B);
        bulkcp(dst, Bblob + (size_t)nblk * BLK_B + (size_t)kt0 * KT_B,
               2 * KT_B, fullB(s));
    };

    if (tid == 0) {
        #pragma unroll
        for (int p = 0; p < PREF; ++p) { issueA(p); issueB(p, 0, hb0); }
    }

    for (int t = 0; t < NSTEPS; ++t) {
        const int v = t & 1;
        const int8_t* Bb  = v ? hb1 : hb0;
        int8_t*       out = v ? hb0 : hb1;
        const int base = t * NIT;

        int C1[2][4] = {};
        int C2[2][4] = {};

        for (int it = 0; it < NIT; ++it) {
            const int j = base + it;
            if (tid == 0 && it + PREF < NIT) {
                issueA(j + PREF);
                issueB(j + PREF, t, Bb);
            }
            const int s = j % STAGES;
            const uint32_t par = (uint32_t)((j / STAGES) & 1);
            mbar_wait(fullA(s), par);
            mbar_wait(fullB(s), par);
            // TMA finished reading h tiles 2it, 2it+1 from global
            if (tid == 0) {
                atomicAdd(&g_rcnt[v * 128 + nblk * 32 + 2 * it], 1);
                atomicAdd(&g_rcnt[v * 128 + nblk * 32 + 2 * it + 1], 1);
            }

            const uint32_t st = sbase + SM_STAGE0 + s * STAGE_BYTES;
            #pragma unroll
            for (int h = 0; h < 2; ++h) {
                const uint32_t sA1 = st + h * KT_B;
                const uint32_t sB1 = st + 2 * KT_B + h * KT_B;
                #pragma unroll
                for (int kk = 0; kk < 2; ++kk) {
                    const uint32_t ka = ((kk * 32) | achk) ^ aswz;
                    const uint32_t kb2 = ((kk * 32) | bchk) ^ bswz;
                    uint32_t a1f[4], a2f[4], b1f[4], b2f[4];
                    ldsm_x4(a1f, sA1 + arow + ka);
                    ldsm_x4(a2f, sA1 + TILE_B + arow + ka);
                    ldsm_x4(b1f, sB1 + brow + kb2);
                    ldsm_x4(b2f, sB1 + TILE_B + brow + kb2);
                    #pragma unroll
                    for (int nt = 0; nt < 2; ++nt) {
                        mma_s8(C1[nt], a1f, &b1f[nt * 2]);
                        mma_s8(C2[nt], a1f, &b2f[nt * 2]);
                        mma_s8(C2[nt], a2f, &b1f[nt * 2]);
                    }
                }
            }
            if (lane == 0) mbar_arrive(emptyb(s));
        }

        // prefetch next step's weight stages (no data dependency)
        if (tid == 0 && t + 1 < NSTEPS) {
            #pragma unroll
            for (int p = 0; p < PREF; ++p) issueA(base + NIT + p);
        }

        // ---- epilogue: wait WAR clearance, write tile, release flag ----
        const int w = (t + 1) & 1;                // buffer being written
        const int r = (t + 1 - w) >> 1;           // completed read-steps of w
        if (tid == 0) {
            const int* rc = &g_rcnt[w * 128 + nblk * 32 + mblk];
            while (ld_acq(rc) < 32 * r) {}
        }
        __syncthreads();

        int8_t* stg = (int8_t*)sm + SM_STG;
        #pragma unroll
        for (int nt = 0; nt < 2; ++nt) {
            const int lr = wm0 + (lane >> 2);
            const int lc = wn0 + nt * 8 + 2 * (lane & 3);
            float vv[4];
            #pragma unroll
            for (int q = 0; q < 4; ++q)
                vv[q] = tanhf(sAB * ((float)C1[nt][q] +
                                     (float)C2[nt][q] * (1.0f / 256.0f)) +
                              cb[nt][q]) * 127.0f;
            #pragma unroll
            for (int q = 0; q < 4; ++q) {
                const int rr = lr + (q >> 1) * 8;
                const int cc = lc + (q & 1);
                int8_t d1, d2;
                quant2(vv[q], d1, d2);
                const uint32_t o = tswz(cc, rr);
                stg[o] = d1;
                stg[o + TILE_B] = d2;
            }
        }
        __syncthreads();
        int8_t* dstb = out + (size_t)nblk * BLK_B + (size_t)mblk * KT_B;
        *(uint4*)&dstb[tid * 16] = *(const uint4*)&stg[tid * 16];
        __syncthreads();
        if (tid == 0) {
            __threadfence();
            st_rel(&g_wflag[w * 128 + nblk * 32 + mblk], t + 1);
        }

        // issue next step's first B stages (spins on producer flags)
        if (tid == 0 && t + 1 < NSTEPS) {
            const int8_t* nB = ((t + 1) & 1) ? hb1 : hb0;
            #pragma unroll
            for (int p = 0; p < PREF; ++p)
                issueB(base + NIT + p, t + 1, nB);
        }
    }
}

// ---------------------------------------------------------------- softmax
__global__ __launch_bounds__(256) void softmax_kernel(
    const float* __restrict__ p, float* __restrict__ out)
{
    const int row  = blockIdx.x * 8 + (threadIdx.x >> 5);
    const int lane = threadIdx.x & 31;
    const float* pr = p + (size_t)row * NDIM;
    float v[8];
    float mx = -INFINITY;
    #pragma unroll
    for (int i = 0; i < 8; ++i) { v[i] = pr[lane + 32 * i]; mx = fmaxf(mx, v[i]); }
    #pragma unroll
    for (int o = 16; o > 0; o >>= 1) mx = fmaxf(mx, __shfl_xor_sync(~0u, mx, o));
    float s = 0.f;
    #pragma unroll
    for (int i = 0; i < 8; ++i) { v[i] = expf(v[i] - mx); s += v[i]; }
    #pragma unroll
    for (int o = 16; o > 0; o >>= 1) s += __shfl_xor_sync(~0u, s, o);
    const float inv = 1.0f / s;
    float* orow = out + (size_t)row * NDIM;
    #pragma unroll
    for (int i = 0; i < 8; ++i) orow[lane + 32 * i] = v[i] * inv;
}

// ---------------------------------------------------------------- launch
extern "C" void kernel_launch(void* const* d_in, const int* in_sizes, int n_in,
                              void* d_out, int out_size)
{
    const float* x   = (const float*)d_in[0];
    const float* Whx = (const float*)d_in[1];
    const float* Whh = (const float*)d_in[2];
    const float* Wph = (const float*)d_in[3];
    const float* bh  = (const float*)d_in[4];
    const float* bp  = (const float*)d_in[5];

    int8_t *whx, *whh, *wph, *xb, *h0, *h1;
    float *c, *p;
    int* maxbits;
    cudaGetSymbolAddress((void**)&whx, g_Whx);
    cudaGetSymbolAddress((void**)&whh, g_Whh);
    cudaGetSymbolAddress((void**)&wph, g_Wph);
    cudaGetSymbolAddress((void**)&xb,  g_x);
    cudaGetSymbolAddress((void**)&h0,  g_h0);
    cudaGetSymbolAddress((void**)&h1,  g_h1);
    cudaGetSymbolAddress((void**)&c,   g_c);
    cudaGetSymbolAddress((void**)&p,   g_p);
    cudaGetSymbolAddress((void**)&maxbits, g_maxbits);

    cudaFuncSetAttribute(rnn_gemm, cudaFuncAttributeMaxDynamicSharedMemorySize,
                         SMEM_BYTES);
    cudaFuncSetAttribute(rnn_steps, cudaFuncAttributeMaxDynamicSharedMemorySize,
                         SMEM_BYTES);

    reset_kernel<<<1, 256>>>();
    maxabs_kernel<<<dim3(2048, 4), 256>>>(Whx, Whh, Wph, x);
    quant_kernel<<<dim3((MDIM * KDIM + 255) / 256, 4), 256>>>(Whx, Whh, Wph, x);

    const dim3 grid(NDIM / BN, MDIM / BM);   // (4, 32) = 128 CTAs

    // c = Whx @ x
    rnn_gemm<<<grid, THREADS, SMEM_BYTES>>>(whx, xb, maxbits + 0, maxbits + 3,
                                            nullptr, c, 0);

    // step 1: h1 = tanh(c + bh) (h0 = 0) -> h blob 0
    first_step_kernel<<<(MDIM * NDIM + 255) / 256, 256>>>(c, bh, h0);

    // steps 2..256: persistent, flag-synchronized; final h in h1
    rnn_steps<<<grid, THREADS, SMEM_BYTES>>>(whh, h0, h1, maxbits + 1, c, bh);

    // p = Wph @ h + bp; softmax
    rnn_gemm<<<grid, THREADS, SMEM_BYTES>>>(wph, h1, maxbits + 2, nullptr,
                                            bp, p, 1);
    softmax_kernel<<<MDIM / 8, 256>>>(p, (float*)d_out);
}

// round 17
// speedup vs baseline: 1.4387x; 1.4387x over previous
#include <cuda_runtime.h>
#include <math.h>
#include <stdint.h>

// ---------------------------------------------------------------- dims
constexpr int MDIM = 2048, KDIM = 2048, NDIM = 256;

// ---------------------------------------------------------------- tiling
constexpr int BM = 64, BN = 64;
constexpr int THREADS = 512;                 // 16 warps: 4 (m) x 4 (n)
constexpr int NWARP = THREADS / 32;
constexpr int NSTEPS = 255;
// packed swizzled tile: 64 rows x 64 B = 4096 B
constexpr int TILE_B = 4096;
constexpr int KT_B   = 2 * TILE_B;           // digit1|digit2 per k64 = 8192
constexpr int BLK_B  = 32 * KT_B;            // per 64-row block = 262144

// ---- single-gemm kernel (c and p) : k128 ring, 5 stages ----
constexpr int G_STAGES = 5;
constexpr int G_PREF = 4;
constexpr int G_NIT = KDIM / 128;            // 16
constexpr int G_STAGE_B = 4 * KT_B;          // 32768
constexpr int G_SMEM = 1024 + G_STAGES * G_STAGE_B;   // 164864

// ---- persistent steps kernel: resident A + k64 ring ----
constexpr int RES_KT = 18;                   // resident weight k-tiles
constexpr int S_STAGES = 4;
constexpr int S_PREF = 3;
constexpr int S_NIT = 32;                    // k64 iterations per step
constexpr int S_STAGE_B = 2 * KT_B;          // B tile + (optional) A tile
constexpr int SM_RES = 1024;
constexpr int SM_SST = SM_RES + RES_KT * KT_B;        // 148480
constexpr int SM_EPI = SM_SST + S_STAGES * S_STAGE_B; // 214016
constexpr int S_SMEM = SM_EPI + 2 * TILE_B;           // 222208

// blobs: [blk64][k64][digit1 4K | digit2 4K]
constexpr size_t WBLOB = 32ull * BLK_B;
constexpr size_t HBLOB = 4ull * BLK_B;

// ---------------------------------------------------------------- scratch
__device__ __align__(128) int8_t g_Whx[WBLOB];
__device__ __align__(128) int8_t g_Whh[WBLOB];
__device__ __align__(128) int8_t g_Wph[WBLOB];
__device__ __align__(128) int8_t g_x [HBLOB];
__device__ __align__(128) int8_t g_h0[HBLOB];
__device__ __align__(128) int8_t g_h1[HBLOB];
__device__ float g_c[MDIM * NDIM];
__device__ float g_p[MDIM * NDIM];
__device__ int   g_maxbits[4];
__device__ unsigned g_bar;

// swizzled byte offset within a packed tile
__device__ __forceinline__ uint32_t tswz(int row, int col) {
    return (uint32_t)(row * 64 + (((col & 48) ^ (((row >> 1) & 3) << 4)) |
                                  (col & 15)));
}

// ---------------------------------------------------------------- helpers
__device__ __forceinline__ uint32_t smem_u32(const void* p) {
    uint32_t a;
    asm("{ .reg .u64 t; cvta.to.shared.u64 t, %1; cvt.u32.u64 %0, t; }"
        : "=r"(a) : "l"(p));
    return a;
}

__device__ __forceinline__ void mma_s8(int* c, const uint32_t* a,
                                       const uint32_t* b) {
    asm volatile(
        "mma.sync.aligned.m16n8k32.row.col.s32.s8.s8.s32 "
        "{%0,%1,%2,%3}, {%4,%5,%6,%7}, {%8,%9}, {%0,%1,%2,%3};"
        : "+r"(c[0]), "+r"(c[1]), "+r"(c[2]), "+r"(c[3])
        : "r"(a[0]), "r"(a[1]), "r"(a[2]), "r"(a[3]), "r"(b[0]), "r"(b[1]));
}

__device__ __forceinline__ void ldsm_x4(uint32_t* r, uint32_t addr) {
    asm volatile("ldmatrix.sync.aligned.m8n8.x4.shared.b16 {%0,%1,%2,%3}, [%4];"
                 : "=r"(r[0]), "=r"(r[1]), "=r"(r[2]), "=r"(r[3]) : "r"(addr));
}

__device__ __forceinline__ void bulkcp(uint32_t sdst, const void* gsrc,
                                       uint32_t bytes, uint32_t mbar) {
    asm volatile(
        "cp.async.bulk.shared::cta.global.mbarrier::complete_tx::bytes "
        "[%0], [%1], %2, [%3];"
        :: "r"(sdst), "l"(gsrc), "r"(bytes), "r"(mbar) : "memory");
}

__device__ __forceinline__ void mbar_init(uint32_t mbar, uint32_t cnt) {
    asm volatile("mbarrier.init.shared.b64 [%0], %1;"
                 :: "r"(mbar), "r"(cnt) : "memory");
}

__device__ __forceinline__ void mbar_expect_tx(uint32_t mbar, uint32_t bytes) {
    asm volatile("mbarrier.arrive.expect_tx.shared.b64 _, [%0], %1;"
                 :: "r"(mbar), "r"(bytes) : "memory");
}

__device__ __forceinline__ void mbar_arrive(uint32_t mbar) {
    asm volatile("mbarrier.arrive.shared.b64 _, [%0];"
                 :: "r"(mbar) : "memory");
}

__device__ __forceinline__ void mbar_wait(uint32_t mb, uint32_t parity) {
    asm volatile(
        "{\n\t.reg .pred P;\n\t"
        "L0_%=:\n\t"
        "mbarrier.try_wait.parity.acquire.cta.shared::cta.b64 P, [%0], %1, 0x989680;\n\t"
        "@P bra.uni L1_%=;\n\t"
        "bra.uni L0_%=;\n\t"
        "L1_%=:\n\t}"
        :: "r"(mb), "r"(parity) : "memory");
}

__device__ __forceinline__ void mbar_wait_relaxed(uint32_t mb, uint32_t parity) {
    asm volatile(
        "{\n\t.reg .pred P;\n\t"
        "L0_%=:\n\t"
        "mbarrier.try_wait.parity.relaxed.cta.shared::cta.b64 P, [%0], %1, 0x989680;\n\t"
        "@P bra.uni L1_%=;\n\t"
        "bra.uni L0_%=;\n\t"
        "L1_%=:\n\t}"
        :: "r"(mb), "r"(parity) : "memory");
}

__device__ __forceinline__ void quant2(float q, int8_t& d1, int8_t& d2) {
    float b1 = rintf(q);
    float b2 = rintf((q - b1) * 256.0f);
    b2 = fminf(fmaxf(b2, -127.0f), 127.0f);
    d1 = (int8_t)(int)b1;
    d2 = (int8_t)(int)b2;
}

// ---------------------------------------------------------------- prep
__global__ void reset_kernel() {
    if (threadIdx.x < 4) g_maxbits[threadIdx.x] = 0;
    if (threadIdx.x == 4) g_bar = 0u;
}

__global__ void maxabs_kernel(const float* __restrict__ w0,
                              const float* __restrict__ w1,
                              const float* __restrict__ w2,
                              const float* __restrict__ x) {
    const int t = blockIdx.y;
    const float* src = (t == 0) ? w0 : (t == 1) ? w1 : (t == 2) ? w2 : x;
    const int len = (t == 3) ? KDIM * NDIM : MDIM * KDIM;
    float m = 0.0f;
    for (int i = blockIdx.x * 256 + threadIdx.x; i < len; i += 2048 * 256)
        m = fmaxf(m, fabsf(src[i]));
    #pragma unroll
    for (int o = 16; o > 0; o >>= 1)
        m = fmaxf(m, __shfl_xor_sync(~0u, m, o));
    if ((threadIdx.x & 31) == 0)
        atomicMax(&g_maxbits[t], __float_as_int(m));
}

__global__ void quant_kernel(const float* __restrict__ w0,
                             const float* __restrict__ w1,
                             const float* __restrict__ w2,
                             const float* __restrict__ x) {
    const int t = blockIdx.y;
    const int len = (t == 3) ? KDIM * NDIM : MDIM * KDIM;
    const int i = blockIdx.x * 256 + threadIdx.x;
    if (i >= len) return;
    const float mx = fmaxf(__int_as_float(g_maxbits[t]), 1e-20f);
    const float iq = 127.0f / mx;
    int8_t d1, d2;
    if (t == 3) {
        const int k = i / NDIM, n = i % NDIM;
        quant2(x[i] * iq, d1, d2);
        const size_t off = (size_t)(n >> 6) * BLK_B + (size_t)(k >> 6) * KT_B +
                           tswz(n & 63, k & 63);
        g_x[off] = d1;
        g_x[off + TILE_B] = d2;
    } else {
        const int m = i >> 11, k = i & 2047;
        const float* w = (t == 0) ? w0 : (t == 1) ? w1 : w2;
        int8_t* o = (t == 0) ? g_Whx : (t == 1) ? g_Whh : g_Wph;
        quant2(w[i] * iq, d1, d2);
        const size_t off = (size_t)(m >> 6) * BLK_B + (size_t)(k >> 6) * KT_B +
                           tswz(m & 63, k & 63);
        o[off] = d1;
        o[off + TILE_B] = d2;
    }
}

__global__ void first_step_kernel(const float* __restrict__ c,
                                  const float* __restrict__ bh,
                                  int8_t* __restrict__ outH) {
    const int i = blockIdx.x * 256 + threadIdx.x;
    if (i >= MDIM * NDIM) return;
    const int n = i >> 11, m = i & 2047;
    const float v = tanhf(c[(size_t)m * NDIM + n] + bh[n]);
    int8_t d1, d2;
    quant2(v * 127.0f, d1, d2);
    const size_t off = (size_t)(n >> 6) * BLK_B + (size_t)(m >> 6) * KT_B +
                       tswz(n & 63, m & 63);
    outH[off] = d1;
    outH[off + TILE_B] = d2;
}

// ---------------------------------------------------------------- single GEMM
__global__ void __launch_bounds__(THREADS) rnn_gemm(
    const int8_t* __restrict__ A, const int8_t* __restrict__ B,
    const int* __restrict__ maxA, const int* __restrict__ maxB,
    const float* __restrict__ bias, float* __restrict__ outF, int mode)
{
    extern __shared__ __align__(16) char sm[];
    const uint32_t sbase = smem_u32(sm);
    const int tid  = threadIdx.x;
    const int lane = tid & 31;
    const int wid  = tid >> 5;
    const int wm0  = (wid & 3) * 16;
    const int wn0  = (wid >> 2) * 16;
    const int mblk = blockIdx.y;
    const int nblk = blockIdx.x;
    const int m0   = mblk * BM;
    const int n0   = nblk * BN;

    auto fullb  = [&](int s) { return sbase + (uint32_t)s * 16; };
    auto emptyb = [&](int s) { return sbase + (uint32_t)s * 16 + 8; };

    const float sa  = __int_as_float(*maxA) * (1.0f / 127.0f);
    const float sb  = maxB ? __int_as_float(*maxB) * (1.0f / 127.0f)
                           : (1.0f / 127.0f);
    const float sAB = sa * sb;

    int C1[2][4] = {};
    int C2[2][4] = {};

    const uint32_t arow = (uint32_t)((wm0 + (lane & 15)) * 64);
    const uint32_t achk = (uint32_t)((lane >> 4) * 16);
    const uint32_t aswz = (uint32_t)((((lane & 15) >> 1) & 3) << 4);
    const uint32_t brow = (uint32_t)((wn0 + (lane & 7) + ((lane >> 4) & 1) * 8) * 64);
    const uint32_t bchk = (uint32_t)(((lane >> 3) & 1) * 16);
    const uint32_t bswz = (uint32_t)(((((lane & 7) + ((lane >> 4) & 1) * 8) >> 1) & 3) << 4);

    if (tid == 0) {
        #pragma unroll
        for (int s = 0; s < G_STAGES; ++s) {
            mbar_init(fullb(s), 1);
            mbar_init(emptyb(s), NWARP);
        }
        asm volatile("fence.proxy.async.shared::cta;" ::: "memory");
    }
    __syncthreads();

    auto issue_stage = [&](int j) {
        const int s = j % G_STAGES;
        if (j >= G_STAGES)
            mbar_wait_relaxed(emptyb(s), (uint32_t)((j / G_STAGES - 1) & 1));
        const uint32_t dst = sbase + 1024 + s * G_STAGE_B;
        mbar_expect_tx(fullb(s), G_STAGE_B);
        bulkcp(dst, A + (size_t)mblk * BLK_B + (size_t)(2 * j) * KT_B,
               2 * KT_B, fullb(s));
        bulkcp(dst + 2 * KT_B, B + (size_t)nblk * BLK_B + (size_t)(2 * j) * KT_B,
               2 * KT_B, fullb(s));
    };

    if (tid == 0) {
        #pragma unroll
        for (int s = 0; s < G_PREF; ++s) issue_stage(s);
    }

    for (int it = 0; it < G_NIT; ++it) {
        if (tid == 0 && it + G_PREF < G_NIT) issue_stage(it + G_PREF);
        const int s = it % G_STAGES;
        mbar_wait(fullb(s), (uint32_t)((it / G_STAGES) & 1));
        const uint32_t st = sbase + 1024 + s * G_STAGE_B;
        #pragma unroll
        for (int h = 0; h < 2; ++h) {
            const uint32_t sA1 = st + h * KT_B;
            const uint32_t sB1 = st + 2 * KT_B + h * KT_B;
            #pragma unroll
            for (int kk = 0; kk < 2; ++kk) {
                const uint32_t ka = ((kk * 32) | achk) ^ aswz;
                const uint32_t kb2 = ((kk * 32) | bchk) ^ bswz;
                uint32_t a1f[4], a2f[4], b1f[4], b2f[4];
                ldsm_x4(a1f, sA1 + arow + ka);
                ldsm_x4(a2f, sA1 + TILE_B + arow + ka);
                ldsm_x4(b1f, sB1 + brow + kb2);
                ldsm_x4(b2f, sB1 + TILE_B + brow + kb2);
                #pragma unroll
                for (int nt = 0; nt < 2; ++nt) {
                    mma_s8(C1[nt], a1f, &b1f[nt * 2]);
                    mma_s8(C2[nt], a1f, &b2f[nt * 2]);
                    mma_s8(C2[nt], a2f, &b1f[nt * 2]);
                }
            }
        }
        if (lane == 0) mbar_arrive(emptyb(s));
    }

    #pragma unroll
    for (int nt = 0; nt < 2; ++nt) {
        const int lr = wm0 + (lane >> 2);
        const int lc = wn0 + nt * 8 + 2 * (lane & 3);
        const int gm = m0 + lr, gn = n0 + lc;
        float bx = 0.f, by = 0.f;
        if (mode == 1) {
            float2 bv = *(const float2*)(bias + gn);
            bx = bv.x; by = bv.y;
        }
        float2 o0, o1;
        o0.x = sAB * ((float)C1[nt][0] + (float)C2[nt][0] * (1.0f / 256.0f)) + bx;
        o0.y = sAB * ((float)C1[nt][1] + (float)C2[nt][1] * (1.0f / 256.0f)) + by;
        o1.x = sAB * ((float)C1[nt][2] + (float)C2[nt][2] * (1.0f / 256.0f)) + bx;
        o1.y = sAB * ((float)C1[nt][3] + (float)C2[nt][3] * (1.0f / 256.0f)) + by;
        *(float2*)(outF + (size_t)gm * NDIM + gn) = o0;
        *(float2*)(outF + (size_t)(gm + 8) * NDIM + gn) = o1;
    }
}

// ---------------------------------------------------------------- persistent
// 255 steps, one kernel, 128 co-resident CTAs, global counter barrier.
// 18 of 32 weight k-tiles resident in SMEM; 14 A + 32 B tiles streamed/step.
__global__ void __launch_bounds__(THREADS) rnn_steps(
    const int8_t* __restrict__ A,
    int8_t* __restrict__ hb0, int8_t* __restrict__ hb1,
    const int* __restrict__ maxA,
    const float* __restrict__ addc, const float* __restrict__ bias)
{
    extern __shared__ __align__(16) char sm[];
    const uint32_t sbase = smem_u32(sm);
    const int tid  = threadIdx.x;
    const int lane = tid & 31;
    const int wid  = tid >> 5;
    const int wm0  = (wid & 3) * 16;
    const int wn0  = (wid >> 2) * 16;
    const int mblk = blockIdx.y;
    const int nblk = blockIdx.x;
    const int m0   = mblk * BM;
    const int n0   = nblk * BN;

    auto fullb  = [&](int s) { return sbase + (uint32_t)s * 16; };
    auto emptyb = [&](int s) { return sbase + (uint32_t)s * 16 + 8; };
    const uint32_t resmb = sbase + 512;

    const float sa  = __int_as_float(*maxA) * (1.0f / 127.0f);
    const float sAB = sa * (1.0f / 127.0f);

    const uint32_t arow = (uint32_t)((wm0 + (lane & 15)) * 64);
    const uint32_t achk = (uint32_t)((lane >> 4) * 16);
    const uint32_t aswz = (uint32_t)((((lane & 15) >> 1) & 3) << 4);
    const uint32_t brow = (uint32_t)((wn0 + (lane & 7) + ((lane >> 4) & 1) * 8) * 64);
    const uint32_t bchk = (uint32_t)(((lane >> 3) & 1) * 16);
    const uint32_t bswz = (uint32_t)(((((lane & 7) + ((lane >> 4) & 1) * 8) >> 1) & 3) << 4);

    // hoist c + bh (constant across steps)
    float cb[2][4];
    #pragma unroll
    for (int nt = 0; nt < 2; ++nt) {
        const int gm = m0 + wm0 + (lane >> 2);
        const int gn = n0 + wn0 + nt * 8 + 2 * (lane & 3);
        float2 c0 = *(const float2*)(addc + (size_t)gm * NDIM + gn);
        float2 c1 = *(const float2*)(addc + (size_t)(gm + 8) * NDIM + gn);
        float2 bv = *(const float2*)(bias + gn);
        cb[nt][0] = c0.x + bv.x;
        cb[nt][1] = c0.y + bv.y;
        cb[nt][2] = c1.x + bv.x;
        cb[nt][3] = c1.y + bv.y;
    }

    if (tid == 0) {
        #pragma unroll
        for (int s = 0; s < S_STAGES; ++s) {
            mbar_init(fullb(s), 1);
            mbar_init(emptyb(s), NWARP);
        }
        mbar_init(resmb, 1);
        asm volatile("fence.proxy.async.shared::cta;" ::: "memory");
    }
    __syncthreads();

    const int8_t* Ab = A + (size_t)mblk * BLK_B;

    // resident weight load (once)
    if (tid == 0) {
        mbar_expect_tx(resmb, RES_KT * KT_B);
        #pragma unroll
        for (int kt = 0; kt < RES_KT; ++kt)
            bulkcp(sbase + SM_RES + kt * KT_B, Ab + (size_t)kt * KT_B,
                   KT_B, resmb);
    }

    // stage issue: B always; A only for kt >= RES_KT
    auto issue = [&](int j, const int8_t* Bblob) {
        const int s = j & (S_STAGES - 1);
        if (j >= S_STAGES)
            mbar_wait_relaxed(emptyb(s), (uint32_t)(((j >> 2) - 1) & 1));
        const int kt = j & 31;
        const uint32_t dst = sbase + SM_SST + s * S_STAGE_B;
        const uint32_t bytes = (kt >= RES_KT) ? 2 * KT_B : KT_B;
        mbar_expect_tx(fullb(s), bytes);
        bulkcp(dst, Bblob + (size_t)nblk * BLK_B + (size_t)kt * KT_B,
               KT_B, fullb(s));
        if (kt >= RES_KT)
            bulkcp(dst + KT_B, Ab + (size_t)kt * KT_B, KT_B, fullb(s));
    };

    if (tid == 0) {
        #pragma unroll
        for (int p = 0; p < S_PREF; ++p) issue(p, hb0);
    }
    mbar_wait(resmb, 0);   // resident weights ready (all threads)

    for (int t = 0; t < NSTEPS; ++t) {
        const int v = t & 1;
        const int8_t* Bb  = v ? hb1 : hb0;
        int8_t*       out = v ? hb0 : hb1;
        const int base = t * S_NIT;

        int C1[2][4] = {};
        int C2[2][4] = {};

        for (int it = 0; it < S_NIT; ++it) {
            const int j = base + it;
            if (tid == 0 && it + S_PREF < S_NIT) issue(j + S_PREF, Bb);
            const int s = j & (S_STAGES - 1);
            mbar_wait(fullb(s), (uint32_t)((j >> 2) & 1));

            const uint32_t bptr = sbase + SM_SST + s * S_STAGE_B;
            const uint32_t aptr = (it < RES_KT)
                                ? (sbase + SM_RES + it * KT_B)
                                : (bptr + KT_B);
            #pragma unroll
            for (int kk = 0; kk < 2; ++kk) {
                const uint32_t ka = ((kk * 32) | achk) ^ aswz;
                const uint32_t kb2 = ((kk * 32) | bchk) ^ bswz;
                uint32_t a1f[4], a2f[4], b1f[4], b2f[4];
                ldsm_x4(a1f, aptr + arow + ka);
                ldsm_x4(a2f, aptr + TILE_B + arow + ka);
                ldsm_x4(b1f, bptr + brow + kb2);
                ldsm_x4(b2f, bptr + TILE_B + brow + kb2);
                #pragma unroll
                for (int nt = 0; nt < 2; ++nt) {
                    mma_s8(C1[nt], a1f, &b1f[nt * 2]);
                    mma_s8(C2[nt], a1f, &b2f[nt * 2]);
                    mma_s8(C2[nt], a2f, &b1f[nt * 2]);
                }
            }
            if (lane == 0) mbar_arrive(emptyb(s));
        }

        // ---- epilogue: h' = tanh(D + c + bh) -> quantized blob tile ----
        int8_t* stg = (int8_t*)sm + SM_EPI;
        #pragma unroll
        for (int nt = 0; nt < 2; ++nt) {
            const int lr = wm0 + (lane >> 2);
            const int lc = wn0 + nt * 8 + 2 * (lane & 3);
            float vv[4];
            #pragma unroll
            for (int q = 0; q < 4; ++q)
                vv[q] = tanhf(sAB * ((float)C1[nt][q] +
                                     (float)C2[nt][q] * (1.0f / 256.0f)) +
                              cb[nt][q]) * 127.0f;
            #pragma unroll
            for (int q = 0; q < 4; ++q) {
                const int rr = lr + (q >> 1) * 8;
                const int cc = lc + (q & 1);
                int8_t d1, d2;
                quant2(vv[q], d1, d2);
                const uint32_t o = tswz(cc, rr);
                stg[o] = d1;
                stg[o + TILE_B] = d2;
            }
        }
        __syncthreads();
        int8_t* dstb = out + (size_t)nblk * BLK_B + (size_t)mblk * KT_B;
        *(uint4*)&dstb[tid * 16] = *(const uint4*)&stg[tid * 16];
        __syncthreads();

        // ---- global step barrier ----
        if (tid == 0) {
            __threadfence();
            atomicAdd(&g_bar, 1u);
            const unsigned target = 128u * (unsigned)(t + 1);
            unsigned w;
            do {
                asm volatile("ld.global.acquire.gpu.u32 %0, [%1];"
                             : "=r"(w) : "l"(&g_bar));
            } while (w < target);
        }
        __syncthreads();

        // issue next step's first B stages
        if (tid == 0 && t + 1 < NSTEPS) {
            const int8_t* nB = ((t + 1) & 1) ? hb1 : hb0;
            #pragma unroll
            for (int p = 0; p < S_PREF; ++p) issue(base + S_NIT + p, nB);
        }
    }
}

// ---------------------------------------------------------------- softmax
__global__ __launch_bounds__(256) void softmax_kernel(
    const float* __restrict__ p, float* __restrict__ out)
{
    const int row  = blockIdx.x * 8 + (threadIdx.x >> 5);
    const int lane = threadIdx.x & 31;
    const float* pr = p + (size_t)row * NDIM;
    float v[8];
    float mx = -INFINITY;
    #pragma unroll
    for (int i = 0; i < 8; ++i) { v[i] = pr[lane + 32 * i]; mx = fmaxf(mx, v[i]); }
    #pragma unroll
    for (int o = 16; o > 0; o >>= 1) mx = fmaxf(mx, __shfl_xor_sync(~0u, mx, o));
    float s = 0.f;
    #pragma unroll
    for (int i = 0; i < 8; ++i) { v[i] = expf(v[i] - mx); s += v[i]; }
    #pragma unroll
    for (int o = 16; o > 0; o >>= 1) s += __shfl_xor_sync(~0u, s, o);
    const float inv = 1.0f / s;
    float* orow = out + (size_t)row * NDIM;
    #pragma unroll
    for (int i = 0; i < 8; ++i) orow[lane + 32 * i] = v[i] * inv;
}

// ---------------------------------------------------------------- launch
extern "C" void kernel_launch(void* const* d_in, const int* in_sizes, int n_in,
                              void* d_out, int out_size)
{
    const float* x   = (const float*)d_in[0];
    const float* Whx = (const float*)d_in[1];
    const float* Whh = (const float*)d_in[2];
    const float* Wph = (const float*)d_in[3];
    const float* bh  = (const float*)d_in[4];
    const float* bp  = (const float*)d_in[5];

    int8_t *whx, *whh, *wph, *xb, *h0, *h1;
    float *c, *p;
    int* maxbits;
    cudaGetSymbolAddress((void**)&whx, g_Whx);
    cudaGetSymbolAddress((void**)&whh, g_Whh);
    cudaGetSymbolAddress((void**)&wph, g_Wph);
    cudaGetSymbolAddress((void**)&xb,  g_x);
    cudaGetSymbolAddress((void**)&h0,  g_h0);
    cudaGetSymbolAddress((void**)&h1,  g_h1);
    cudaGetSymbolAddress((void**)&c,   g_c);
    cudaGetSymbolAddress((void**)&p,   g_p);
    cudaGetSymbolAddress((void**)&maxbits, g_maxbits);

    cudaFuncSetAttribute(rnn_gemm, cudaFuncAttributeMaxDynamicSharedMemorySize,
                         G_SMEM);
    cudaFuncSetAttribute(rnn_steps, cudaFuncAttributeMaxDynamicSharedMemorySize,
                         S_SMEM);

    reset_kernel<<<1, 32>>>();
    maxabs_kernel<<<dim3(2048, 4), 256>>>(Whx, Whh, Wph, x);
    quant_kernel<<<dim3((MDIM * KDIM + 255) / 256, 4), 256>>>(Whx, Whh, Wph, x);

    const dim3 grid(NDIM / BN, MDIM / BM);   // (4, 32) = 128 CTAs

    // c = Whx @ x
    rnn_gemm<<<grid, THREADS, G_SMEM>>>(whx, xb, maxbits + 0, maxbits + 3,
                                        nullptr, c, 0);

    // step 1: h1 = tanh(c + bh) (h0 = 0) -> h blob 0
    first_step_kernel<<<(MDIM * NDIM + 255) / 256, 256>>>(c, bh, h0);

    // steps 2..256: persistent, resident-weight; final h in h1
    rnn_steps<<<grid, THREADS, S_SMEM>>>(whh, h0, h1, maxbits + 1, c, bh);

    // p = Wph @ h + bp; softmax
    rnn_gemm<<<grid, THREADS, G_SMEM>>>(wph, h1, maxbits + 2, nullptr,
                                        bp, p, 1);
    softmax_kernel<<<MDIM / 8, 256>>>(p, (float*)d_out);
}